// round 16
// baseline (speedup 1.0000x reference)
#include <cuda_runtime.h>
#include <cuda_bf16.h>
#include <cstdint>

#define B_   4
#define S_   2048
#define HID_ 768
#define NH_  12
#define HD_  64
#define M_   (B_ * S_)   // 8192
#define BH_  (B_ * NH_)  // 48
#define WN_  (HID_ * HID_)
#define LOG2E 1.4426950408889634f

// ---------------- scratch (device globals; no allocation allowed) ----------
__device__ __nv_bfloat16 g_xh[(size_t)M_ * HID_];
__device__ __nv_bfloat16 g_xl[(size_t)M_ * HID_];
__device__ __nv_bfloat16 g_Wh[(size_t)4 * WN_];       // q,k,v,o  [k][n]
__device__ __nv_bfloat16 g_Wl[(size_t)4 * WN_];
__device__ __nv_bfloat16 g_Qh[(size_t)BH_ * S_ * HD_];
__device__ __nv_bfloat16 g_Ql[(size_t)BH_ * S_ * HD_];
__device__ __nv_bfloat16 g_Kh[(size_t)BH_ * S_ * HD_];
__device__ __nv_bfloat16 g_Kl[(size_t)BH_ * S_ * HD_];
__device__ __nv_bfloat16 g_Vh[(size_t)BH_ * S_ * HD_];
__device__ __nv_bfloat16 g_Vl[(size_t)BH_ * S_ * HD_];
__device__ __nv_bfloat16 g_ctxh[(size_t)M_ * HID_];
__device__ __nv_bfloat16 g_ctxl[(size_t)M_ * HID_];

// ---------------- common helpers -------------------------------------------
__device__ __forceinline__ void split2(float a, float b, uint32_t& hi, uint32_t& lo)
{
    uint32_t h;
    asm("cvt.rn.bf16x2.f32 %0, %1, %2;" : "=r"(h) : "f"(b), "f"(a));
    float ha = __uint_as_float(h << 16);
    float hb = __uint_as_float(h & 0xffff0000u);
    float ra = a - ha;
    float rb = b - hb;
    uint32_t l;
    asm("cvt.rn.bf16x2.f32 %0, %1, %2;" : "=r"(l) : "f"(rb), "f"(ra));
    hi = h;
    lo = l;
}
__device__ __forceinline__ float ex2f(float x)
{
    float y;
    asm("ex2.approx.ftz.f32 %0, %1;" : "=f"(y) : "f"(x));
    return y;
}

__device__ __forceinline__ void ldsm_x4(uint32_t* r, uint32_t addr)
{
    asm volatile("ldmatrix.sync.aligned.m8n8.x4.shared.b16 {%0,%1,%2,%3}, [%4];"
                 : "=r"(r[0]), "=r"(r[1]), "=r"(r[2]), "=r"(r[3]) : "r"(addr));
}
__device__ __forceinline__ void ldsm_x4t(uint32_t* r, uint32_t addr)
{
    asm volatile("ldmatrix.sync.aligned.m8n8.x4.trans.shared.b16 {%0,%1,%2,%3}, [%4];"
                 : "=r"(r[0]), "=r"(r[1]), "=r"(r[2]), "=r"(r[3]) : "r"(addr));
}
__device__ __forceinline__ void ldsm_x2t(uint32_t* r, uint32_t addr)
{
    asm volatile("ldmatrix.sync.aligned.m8n8.x2.trans.shared.b16 {%0,%1}, [%2];"
                 : "=r"(r[0]), "=r"(r[1]) : "r"(addr));
}
__device__ __forceinline__ void mma16816(float* c, const uint32_t* a, uint32_t b0, uint32_t b1)
{
    asm volatile(
        "mma.sync.aligned.m16n8k16.row.col.f32.bf16.bf16.f32 "
        "{%0,%1,%2,%3},{%4,%5,%6,%7},{%8,%9},{%0,%1,%2,%3};"
        : "+f"(c[0]), "+f"(c[1]), "+f"(c[2]), "+f"(c[3])
        : "r"(a[0]), "r"(a[1]), "r"(a[2]), "r"(a[3]), "r"(b0), "r"(b1));
}
__device__ __forceinline__ void cpasync16(uint32_t dst, const void* src)
{
    asm volatile("cp.async.cg.shared.global [%0], [%1], 16;" :: "r"(dst), "l"(src));
}

// ---------------- pre-split: fp32 -> bf16 hi/lo -----------------------------
__global__ __launch_bounds__(256) void split_x(
    const float* __restrict__ src, __nv_bfloat16* __restrict__ dh,
    __nv_bfloat16* __restrict__ dl)
{
    int i = blockIdx.x * blockDim.x + threadIdx.x;
    float2 v = ((const float2*)src)[i];
    uint32_t h, l;
    split2(v.x, v.y, h, l);
    ((uint32_t*)dh)[i] = h;
    ((uint32_t*)dl)[i] = l;
}

__global__ __launch_bounds__(256) void split_w4(
    const float* __restrict__ s0, const float* __restrict__ s1,
    const float* __restrict__ s2, const float* __restrict__ s3)
{
    int i = blockIdx.x * blockDim.x + threadIdx.x;
    int z = i / (WN_ / 2);
    int r = i - z * (WN_ / 2);
    const float* src = (z == 0) ? s0 : ((z == 1) ? s1 : ((z == 2) ? s2 : s3));
    float2 v = ((const float2*)src)[r];
    uint32_t h, l;
    split2(v.x, v.y, h, l);
    ((uint32_t*)g_Wh)[i] = h;
    ((uint32_t*)g_Wl)[i] = l;
}

// ============================================================================
// pure-bf16 3-term GEMM (R9 proven, R14 fast split2)
// ============================================================================
#define AKP 40
#define BNP 136
#define OFF_AHI 0
#define OFF_ALO 5120
#define OFF_BHI 10240
#define OFF_BLO 14592
#define STG     18944
#define SMEM_G  (2 * STG * 2)

__device__ __forceinline__ void bgemm_body(
    const __nv_bfloat16* __restrict__ Ah, const __nv_bfloat16* __restrict__ Al,
    const __nv_bfloat16* __restrict__ Wh, const __nv_bfloat16* __restrict__ Wl,
    const float* __restrict__ bias,
    float* __restrict__ Cf,
    __nv_bfloat16* __restrict__ Ch, __nv_bfloat16* __restrict__ Cl,
    float scale, int bm, int bn)
{
    extern __shared__ char smg[];
    uint32_t smbase = (uint32_t)__cvta_generic_to_shared(smg);

    int tid = threadIdx.x, lane = tid & 31, wid = tid >> 5;
    int g = lane >> 2, tig = lane & 3;
    int wm = (wid & 1) * 64, wn = (wid >> 1) * 32;

    float acc[4][4][4];
#pragma unroll
    for (int mi = 0; mi < 4; mi++)
#pragma unroll
        for (int nj = 0; nj < 4; nj++)
#pragma unroll
            for (int q = 0; q < 4; q++) acc[mi][nj][q] = 0.f;

    auto issue_g = [&](int kt, int buf) {
        uint32_t sb = smbase + buf * (STG * 2);
#pragma unroll
        for (int i = 0; i < 4; i++) {
            int idx = i * 256 + tid;
            const __nv_bfloat16* base = (idx < 512) ? Ah : Al;
            uint32_t off = (idx < 512) ? OFF_AHI : OFF_ALO;
            int c = idx & 511;
            int row = c >> 2, kc = c & 3;
            cpasync16(sb + (off + row * AKP + kc * 8) * 2,
                      base + (size_t)(bm * 128 + row) * HID_ + kt * 32 + kc * 8);
        }
#pragma unroll
        for (int i = 0; i < 4; i++) {
            int idx = i * 256 + tid;
            const __nv_bfloat16* base = (idx < 512) ? Wh : Wl;
            uint32_t off = (idx < 512) ? OFF_BHI : OFF_BLO;
            int c = idx & 511;
            int row = c >> 4, nc = c & 15;
            cpasync16(sb + (off + row * BNP + nc * 8) * 2,
                      base + (size_t)(kt * 32 + row) * HID_ + bn * 128 + nc * 8);
        }
    };

    auto mma_tile = [&](int buf) {
        uint32_t abase = smbase + buf * (STG * 2);
        int arow = lane & 15;
        int asel = (lane >> 4) * 8;
#pragma unroll
        for (int ks = 0; ks < 32; ks += 16) {
            uint32_t ah[4][4], bh[4][2], bl[4][2];
            int ak = ks + asel;
            int bk = ks + (lane & 15);
#pragma unroll
            for (int mi = 0; mi < 4; mi++)
                ldsm_x4(ah[mi], abase + (uint32_t)(((wm + mi * 16 + arow) * AKP + ak) * 2));
#pragma unroll
            for (int nj = 0; nj < 4; nj++) {
                uint32_t ba = abase + (uint32_t)((bk * BNP + wn + nj * 8) * 2);
                ldsm_x2t(bh[nj], ba + OFF_BHI * 2);
                ldsm_x2t(bl[nj], ba + OFF_BLO * 2);
            }
#pragma unroll
            for (int mi = 0; mi < 4; mi++)
#pragma unroll
                for (int nj = 0; nj < 4; nj++) mma16816(acc[mi][nj], ah[mi], bh[nj][0], bh[nj][1]);
#pragma unroll
            for (int mi = 0; mi < 4; mi++)
#pragma unroll
                for (int nj = 0; nj < 4; nj++) mma16816(acc[mi][nj], ah[mi], bl[nj][0], bl[nj][1]);
#pragma unroll
            for (int mi = 0; mi < 4; mi++)
                ldsm_x4(ah[mi], abase + (uint32_t)((OFF_ALO + (wm + mi * 16 + arow) * AKP + ak) * 2));
#pragma unroll
            for (int mi = 0; mi < 4; mi++)
#pragma unroll
                for (int nj = 0; nj < 4; nj++) mma16816(acc[mi][nj], ah[mi], bh[nj][0], bh[nj][1]);
        }
    };

    issue_g(0, 0);
    asm volatile("cp.async.commit_group;");

    int buf = 0;
    for (int kt = 0; kt < HID_ / 32; kt++) {
        if (kt + 1 < HID_ / 32) {
            issue_g(kt + 1, buf ^ 1);
            asm volatile("cp.async.commit_group;");
            asm volatile("cp.async.wait_group 1;");
        } else {
            asm volatile("cp.async.wait_group 0;");
        }
        __syncthreads();
        mma_tile(buf);
        __syncthreads();
        buf ^= 1;
    }

#pragma unroll
    for (int mi = 0; mi < 4; mi++) {
#pragma unroll
        for (int nj = 0; nj < 4; nj++) {
            int m0 = bm * 128 + wm + mi * 16 + g;
            int n  = bn * 128 + wn + nj * 8 + 2 * tig;
            float bx = bias[n], by = bias[n + 1];
#pragma unroll
            for (int half = 0; half < 2; half++) {
                int m = m0 + half * 8;
                float vx = (acc[mi][nj][half * 2 + 0] + bx) * scale;
                float vy = (acc[mi][nj][half * 2 + 1] + by) * scale;
                if (Ch) {
                    int b = m >> 11, s = m & (S_ - 1);
                    int h = n >> 6, d = n & 63;
                    size_t dst = (((size_t)b * NH_ + h) * S_ + s) * HD_ + d;
                    uint32_t hi, lo;
                    split2(vx, vy, hi, lo);
                    *(uint32_t*)(Ch + dst) = hi;
                    *(uint32_t*)(Cl + dst) = lo;
                } else {
                    *(float2*)(Cf + (size_t)m * HID_ + n) = make_float2(vx, vy);
                }
            }
        }
    }
}

__global__ void __launch_bounds__(256, 2) bgemm_qkv(
    const float* __restrict__ b0, const float* __restrict__ b1,
    const float* __restrict__ b2)
{
    int z = blockIdx.z;
    const float* bias = (z == 0) ? b0 : ((z == 1) ? b1 : b2);
    __nv_bfloat16* Ch = (z == 0) ? g_Qh : ((z == 1) ? g_Kh : g_Vh);
    __nv_bfloat16* Cl = (z == 0) ? g_Ql : ((z == 1) ? g_Kl : g_Vl);
    float scale = (z == 0) ? 0.125f * LOG2E : 1.0f;
    bgemm_body(g_xh, g_xl, g_Wh + (size_t)z * WN_, g_Wl + (size_t)z * WN_,
               bias, nullptr, Ch, Cl, scale, blockIdx.y, blockIdx.x);
}

__global__ void __launch_bounds__(256, 2) bgemm_out(
    const float* __restrict__ bias, float* __restrict__ C)
{
    bgemm_body(g_ctxh, g_ctxl, g_Wh + (size_t)3 * WN_, g_Wl + (size_t)3 * WN_,
               bias, C, nullptr, nullptr, 1.0f, blockIdx.y, blockIdx.x);
}

// ============================================================================
// HMMA flash attention: 128 threads (4 warps), warp m-tile = 32 q rows.
// np-major software pipeline: per 16-row K chunk {QK mma -> exp -> PV mma}.
// Two-pass softmax (pass1 1-term Kh-only). 2 CTAs/SM, smem 64KB.
// ============================================================================
#define KVB   32768
#define SMEM_ATT (2 * KVB)

__device__ __forceinline__ uint32_t swz(uint32_t row, uint32_t c16)
{
    return row * 128u + (((c16) ^ (row & 7u)) << 4);
}

__global__ void __launch_bounds__(128, 2) attn_kernel(float* __restrict__ attn_out)
{
    extern __shared__ char sma[];
    uint32_t smbase = (uint32_t)__cvta_generic_to_shared(sma);
    int tid = threadIdx.x, lane = tid & 31, w = tid >> 5;   // w in [0,4)
    int g = lane >> 2, tig = lane & 3;
    int qb = blockIdx.x, h = blockIdx.y, b = blockIdx.z;
    int bh = b * NH_ + h;

    // ---- stage split Q (128 rows, 8 blocks of 16 rows) into buffer 0 ----
    {
        const __nv_bfloat16* Qhg = g_Qh + ((size_t)bh * S_ + qb * 128) * HD_;
        const __nv_bfloat16* Qlg = g_Ql + ((size_t)bh * S_ + qb * 128) * HD_;
#pragma unroll
        for (int i = 0; i < 8; i++) {
            int idx = i * 128 + tid;
            int row = idx >> 3, c16 = idx & 7;
            uint32_t off = (row >> 4) * 4096 + swz(row & 15, c16);
            *(float4*)(sma + off)        = *(const float4*)(Qhg + row * 64 + c16 * 8);
            *(float4*)(sma + off + 2048) = *(const float4*)(Qlg + row * 64 + c16 * 8);
        }
    }
    __syncthreads();

    // ---- Q fragments: 2 m16 tiles per warp (rows w*32 .. w*32+31) ----
    uint32_t qh[2][4][4], ql[2][4][4];
    int li = lane >> 3;
    int rl = (lane & 7) + 8 * (li & 1);
#pragma unroll
    for (int mh = 0; mh < 2; mh++) {
        uint32_t QB = smbase + (w * 2 + mh) * 4096;
#pragma unroll
        for (int kst = 0; kst < 4; kst++) {
            int c16 = kst * 2 + (li >> 1);
            ldsm_x4(qh[mh][kst], QB + swz(rl, c16));
            ldsm_x4(ql[mh][kst], QB + 2048 + swz(rl, c16));
        }
    }
    __syncthreads();    // done reading Q before loads overwrite buffer 0

    const size_t bhS = (size_t)bh * S_;

    // pass-1 loader: 256 K rows (Kh only) per buffer, 2048 chunks, 128 thr
    auto issue_k1 = [&](int kb4, int buf) {
        const size_t tb = (bhS + kb4 * 256) * HD_;
#pragma unroll
        for (int i = 0; i < 16; i++) {
            int idx = i * 128 + tid;
            int sub = i >> 2;
            int c = idx & 511;
            int row = c >> 3, c16 = c & 7;
            uint32_t dst = smbase + buf * KVB + sub * 8192 + swz(row, c16);
            const __nv_bfloat16* src = g_Kh + tb + sub * 64 * HD_ + row * 64 + c16 * 8;
            cpasync16(dst, src);
        }
    };
    // pass-2 loader: Kh,Kl,Vh,Vl 64 rows, 2048 chunks, 128 thr
    auto issue_kv = [&](int kb, int buf) {
        const size_t tb = (bhS + kb * 64) * HD_;
#pragma unroll
        for (int i = 0; i < 16; i++) {
            int idx = i * 128 + tid;
            int arr = i >> 2;
            int c = idx & 511;
            int row = c >> 3, c16 = c & 7;
            uint32_t dst = smbase + buf * KVB + arr * 8192 + swz(row, c16);
            const __nv_bfloat16* src;
            if      (arr == 0) src = g_Kh + tb;
            else if (arr == 1) src = g_Kl + tb;
            else if (arr == 2) src = g_Vh + tb;
            else               src = g_Vl + tb;
            src += row * 64 + c16 * 8;
            cpasync16(dst, src);
        }
    };

    // ====== PASS 1: rowsums (1-term, Kh only), 8 its x 256 K rows ======
    float rs[2][2] = {{0.f, 0.f}, {0.f, 0.f}};
    {
        issue_k1(0, 0);
        asm volatile("cp.async.commit_group;");
        int buf = 0;
        for (int kb = 0; kb < 8; kb++) {
            if (kb) __syncthreads();
            if (kb + 1 < 8) {
                issue_k1(kb + 1, buf ^ 1);
                asm volatile("cp.async.commit_group;");
                asm volatile("cp.async.wait_group 1;");
            } else {
                asm volatile("cp.async.wait_group 0;");
            }
            __syncthreads();
            uint32_t kvb = smbase + buf * KVB;
#pragma unroll
            for (int sub = 0; sub < 4; sub++) {
#pragma unroll
                for (int np = 0; np < 4; np++) {
                    float sacc[2][2][4];
#pragma unroll
                    for (int mh = 0; mh < 2; mh++)
#pragma unroll
                        for (int hf = 0; hf < 2; hf++)
#pragma unroll
                            for (int q = 0; q < 4; q++) sacc[mh][hf][q] = 0.f;
#pragma unroll
                    for (int kst = 0; kst < 4; kst++) {
                        int kc = kst * 2 + (li >> 1);
                        uint32_t kh4[4];
                        ldsm_x4(kh4, kvb + sub * 8192 + swz(np * 16 + rl, kc));
#pragma unroll
                        for (int mh = 0; mh < 2; mh++) {
                            mma16816(sacc[mh][0], qh[mh][kst], kh4[0], kh4[2]);
                            mma16816(sacc[mh][1], qh[mh][kst], kh4[1], kh4[3]);
                        }
                    }
#pragma unroll
                    for (int mh = 0; mh < 2; mh++)
#pragma unroll
                        for (int hf = 0; hf < 2; hf++) {
                            rs[mh][0] += ex2f(sacc[mh][hf][0]) + ex2f(sacc[mh][hf][1]);
                            rs[mh][1] += ex2f(sacc[mh][hf][2]) + ex2f(sacc[mh][hf][3]);
                        }
                }
            }
            buf ^= 1;
        }
    }
    float inv[2][2];
#pragma unroll
    for (int mh = 0; mh < 2; mh++)
#pragma unroll
        for (int j = 0; j < 2; j++) {
            float v = rs[mh][j];
            v += __shfl_xor_sync(0xffffffffu, v, 1);
            v += __shfl_xor_sync(0xffffffffu, v, 2);
            inv[mh][j] = 1.0f / v;
        }
    __syncthreads();

    // ====== PASS 2: np-major pipeline {QK(np) -> exp -> PV(np)} ======
    float ctx[2][8][4];
#pragma unroll
    for (int mh = 0; mh < 2; mh++)
#pragma unroll
        for (int nt = 0; nt < 8; nt++)
#pragma unroll
            for (int q = 0; q < 4; q++) ctx[mh][nt][q] = 0.f;

    issue_kv(0, 0);
    asm volatile("cp.async.commit_group;");
    int buf = 0;
    for (int kb = 0; kb < S_ / 64; kb++) {
        if (kb) __syncthreads();
        if (kb + 1 < S_ / 64) {
            issue_kv(kb + 1, buf ^ 1);
            asm volatile("cp.async.commit_group;");
            asm volatile("cp.async.wait_group 1;");
        } else {
            asm volatile("cp.async.wait_group 0;");
        }
        __syncthreads();

        uint32_t kvb = smbase + buf * KVB;

        float* attp0 = nullptr;
        if (attn_out)
            attp0 = attn_out + (bhS + qb * 128 + w * 32 + g) * S_ + kb * 64 + 2 * tig;

#pragma unroll
        for (int np = 0; np < 4; np++) {
            // ---- QK(np): 3-term scores for K rows np*16..np*16+15 ----
            float sacc[2][2][4];
#pragma unroll
            for (int mh = 0; mh < 2; mh++)
#pragma unroll
                for (int hf = 0; hf < 2; hf++)
#pragma unroll
                    for (int q = 0; q < 4; q++) sacc[mh][hf][q] = 0.f;
#pragma unroll
            for (int kst = 0; kst < 4; kst++) {
                int kc = kst * 2 + (li >> 1);
                uint32_t kh4[4], kl4[4];
                ldsm_x4(kh4, kvb +        swz(np * 16 + rl, kc));
                ldsm_x4(kl4, kvb + 8192 + swz(np * 16 + rl, kc));
#pragma unroll
                for (int mh = 0; mh < 2; mh++) {
                    mma16816(sacc[mh][0], qh[mh][kst], kh4[0], kh4[2]);
                    mma16816(sacc[mh][1], qh[mh][kst], kh4[1], kh4[3]);
                    mma16816(sacc[mh][0], qh[mh][kst], kl4[0], kl4[2]);
                    mma16816(sacc[mh][1], qh[mh][kst], kl4[1], kl4[3]);
                    mma16816(sacc[mh][0], ql[mh][kst], kh4[0], kh4[2]);
                    mma16816(sacc[mh][1], ql[mh][kst], kh4[1], kh4[3]);
                }
            }

            // ---- exp/split/attn-store for nt = 2np, 2np+1 ----
            uint32_t pah[2][4], pal[2][4];
#pragma unroll
            for (int mh = 0; mh < 2; mh++) {
                float* attp = attp0 ? attp0 + mh * 16 * S_ : nullptr;
#pragma unroll
                for (int hf = 0; hf < 2; hf++) {
                    int nt = 2 * np + hf;
                    float p0 = ex2f(sacc[mh][hf][0]) * inv[mh][0];
                    float p1 = ex2f(sacc[mh][hf][1]) * inv[mh][0];
                    float p2 = ex2f(sacc[mh][hf][2]) * inv[mh][1];
                    float p3 = ex2f(sacc[mh][hf][3]) * inv[mh][1];
                    if (attp) {
                        __stcs((float2*)(attp + nt * 8),          make_float2(p0, p1));
                        __stcs((float2*)(attp + 8 * S_ + nt * 8), make_float2(p2, p3));
                    }
                    uint32_t h01, l01, h23, l23;
                    split2(p0, p1, h01, l01);
                    split2(p2, p3, h23, l23);
                    pah[mh][hf * 2 + 0] = h01;
                    pah[mh][hf * 2 + 1] = h23;
                    pal[mh][hf * 2 + 0] = l01;
                    pal[mh][hf * 2 + 1] = l23;
                }
            }

            // ---- PV(np): ctx += P(:, np-chunk) @ V(np-chunk rows) ----
            int vr = np * 16 + (lane & 7) + 8 * (li & 1);
#pragma unroll
            for (int nc = 0; nc < 4; nc++) {
                uint32_t vh4[4], vl4[4];
                int vc = nc * 2 + (li >> 1);
                ldsm_x4t(vh4, kvb + 16384 + swz(vr, vc));
                ldsm_x4t(vl4, kvb + 24576 + swz(vr, vc));
#pragma unroll
                for (int mh = 0; mh < 2; mh++) {
                    mma16816(ctx[mh][2 * nc],     pah[mh], vh4[0], vh4[1]);
                    mma16816(ctx[mh][2 * nc + 1], pah[mh], vh4[2], vh4[3]);
                    mma16816(ctx[mh][2 * nc],     pah[mh], vl4[0], vl4[1]);
                    mma16816(ctx[mh][2 * nc + 1], pah[mh], vl4[2], vl4[3]);
                    mma16816(ctx[mh][2 * nc],     pal[mh], vh4[0], vh4[1]);
                    mma16816(ctx[mh][2 * nc + 1], pal[mh], vh4[2], vh4[3]);
                }
            }
        }
        buf ^= 1;
    }

    // ---- store ctx (already normalized) as split bf16 ----
#pragma unroll
    for (int mh = 0; mh < 2; mh++) {
        int qrow0 = qb * 128 + w * 32 + mh * 16 + g;
        size_t base0 = ((size_t)b * S_ + qrow0) * HID_ + h * HD_ + 2 * tig;
#pragma unroll
        for (int nt = 0; nt < 8; nt++) {
            uint32_t hi, lo;
            split2(ctx[mh][nt][0], ctx[mh][nt][1], hi, lo);
            *(uint32_t*)(g_ctxh + base0 + nt * 8) = hi;
            *(uint32_t*)(g_ctxl + base0 + nt * 8) = lo;
            split2(ctx[mh][nt][2], ctx[mh][nt][3], hi, lo);
            *(uint32_t*)(g_ctxh + base0 + 8 * HID_ + nt * 8) = hi;
            *(uint32_t*)(g_ctxl + base0 + 8 * HID_ + nt * 8) = lo;
        }
    }
}

// ---------------- launch ---------------------------------------------------
extern "C" void kernel_launch(void* const* d_in, const int* in_sizes, int n_in,
                              void* d_out, int out_size)
{
    const float* x  = (const float*)d_in[0];
    const float* Wq = (const float*)d_in[1];
    const float* bq = (const float*)d_in[2];
    const float* Wk = (const float*)d_in[3];
    const float* bk = (const float*)d_in[4];
    const float* Wv = (const float*)d_in[5];
    const float* bv = (const float*)d_in[6];
    const float* Wo = (const float*)d_in[7];
    const float* bo = (const float*)d_in[8];

    float* out = (float*)d_out;
    const size_t OUT_E = (size_t)B_ * S_ * HID_;
    const size_t ATT_E = (size_t)B_ * NH_ * S_ * S_;
    float* attn = ((size_t)out_size >= OUT_E + ATT_E) ? (out + OUT_E) : nullptr;

    __nv_bfloat16 *xh, *xl;
    cudaGetSymbolAddress((void**)&xh, g_xh);
    cudaGetSymbolAddress((void**)&xl, g_xl);

    cudaFuncSetAttribute(attn_kernel,
                         cudaFuncAttributeMaxDynamicSharedMemorySize, SMEM_ATT);
    cudaFuncSetAttribute(bgemm_qkv,
                         cudaFuncAttributeMaxDynamicSharedMemorySize, SMEM_G);
    cudaFuncSetAttribute(bgemm_out,
                         cudaFuncAttributeMaxDynamicSharedMemorySize, SMEM_G);

    split_x<<<M_ * HID_ / 512, 256>>>(x, xh, xl);
    split_w4<<<4 * WN_ / 512, 256>>>(Wq, Wk, Wv, Wo);

    dim3 g1(HID_ / 128, M_ / 128, 3);
    bgemm_qkv<<<g1, 256, SMEM_G>>>(bq, bk, bv);

    dim3 g2(S_ / 128, NH_, B_);
    attn_kernel<<<g2, 128, SMEM_ATT>>>(attn);

    dim3 g3(HID_ / 128, M_ / 128);
    bgemm_out<<<g3, 256, SMEM_G>>>(bo, out);
}

// round 17
// speedup vs baseline: 1.0356x; 1.0356x over previous
#include <cuda_runtime.h>
#include <cuda_bf16.h>
#include <cstdint>

#define B_   4
#define S_   2048
#define HID_ 768
#define NH_  12
#define HD_  64
#define M_   (B_ * S_)   // 8192
#define BH_  (B_ * NH_)  // 48
#define WN_  (HID_ * HID_)
#define LOG2E 1.4426950408889634f

// ---------------- scratch (device globals; no allocation allowed) ----------
__device__ __nv_bfloat16 g_xh[(size_t)M_ * HID_];
__device__ __nv_bfloat16 g_xl[(size_t)M_ * HID_];
__device__ __nv_bfloat16 g_Wh[(size_t)4 * WN_];       // q,k,v,o  [k][n]
__device__ __nv_bfloat16 g_Wl[(size_t)4 * WN_];
__device__ __nv_bfloat16 g_Qh[(size_t)BH_ * S_ * HD_];
__device__ __nv_bfloat16 g_Ql[(size_t)BH_ * S_ * HD_];
__device__ __nv_bfloat16 g_Kh[(size_t)BH_ * S_ * HD_];
__device__ __nv_bfloat16 g_Kl[(size_t)BH_ * S_ * HD_];
__device__ __nv_bfloat16 g_Vh[(size_t)BH_ * S_ * HD_];
__device__ __nv_bfloat16 g_Vl[(size_t)BH_ * S_ * HD_];
__device__ __nv_bfloat16 g_ctxh[(size_t)M_ * HID_];
__device__ __nv_bfloat16 g_ctxl[(size_t)M_ * HID_];

// ---------------- common helpers -------------------------------------------
__device__ __forceinline__ void split2(float a, float b, uint32_t& hi, uint32_t& lo)
{
    uint32_t h;
    asm("cvt.rn.bf16x2.f32 %0, %1, %2;" : "=r"(h) : "f"(b), "f"(a));
    float ha = __uint_as_float(h << 16);
    float hb = __uint_as_float(h & 0xffff0000u);
    float ra = a - ha;
    float rb = b - hb;
    uint32_t l;
    asm("cvt.rn.bf16x2.f32 %0, %1, %2;" : "=r"(l) : "f"(rb), "f"(ra));
    hi = h;
    lo = l;
}
__device__ __forceinline__ float ex2f(float x)
{
    float y;
    asm("ex2.approx.ftz.f32 %0, %1;" : "=f"(y) : "f"(x));
    return y;
}

__device__ __forceinline__ void ldsm_x4(uint32_t* r, uint32_t addr)
{
    asm volatile("ldmatrix.sync.aligned.m8n8.x4.shared.b16 {%0,%1,%2,%3}, [%4];"
                 : "=r"(r[0]), "=r"(r[1]), "=r"(r[2]), "=r"(r[3]) : "r"(addr));
}
__device__ __forceinline__ void ldsm_x4t(uint32_t* r, uint32_t addr)
{
    asm volatile("ldmatrix.sync.aligned.m8n8.x4.trans.shared.b16 {%0,%1,%2,%3}, [%4];"
                 : "=r"(r[0]), "=r"(r[1]), "=r"(r[2]), "=r"(r[3]) : "r"(addr));
}
__device__ __forceinline__ void ldsm_x2t(uint32_t* r, uint32_t addr)
{
    asm volatile("ldmatrix.sync.aligned.m8n8.x2.trans.shared.b16 {%0,%1}, [%2];"
                 : "=r"(r[0]), "=r"(r[1]) : "r"(addr));
}
__device__ __forceinline__ void mma16816(float* c, const uint32_t* a, uint32_t b0, uint32_t b1)
{
    asm volatile(
        "mma.sync.aligned.m16n8k16.row.col.f32.bf16.bf16.f32 "
        "{%0,%1,%2,%3},{%4,%5,%6,%7},{%8,%9},{%0,%1,%2,%3};"
        : "+f"(c[0]), "+f"(c[1]), "+f"(c[2]), "+f"(c[3])
        : "r"(a[0]), "r"(a[1]), "r"(a[2]), "r"(a[3]), "r"(b0), "r"(b1));
}
__device__ __forceinline__ void cpasync16(uint32_t dst, const void* src)
{
    asm volatile("cp.async.cg.shared.global [%0], [%1], 16;" :: "r"(dst), "l"(src));
}

// ---------------- pre-split: x and all 4 W in ONE launch --------------------
// grid.x covers x pairs (6144 blocks of 512 pairs... computed at launch);
// blocks beyond x handle the W's.
#define XPAIRS (M_ * HID_ / 2)          // 3,145,728 pairs
#define WPAIRS (4 * WN_ / 2)            // 1,179,648 pairs
__global__ __launch_bounds__(256) void split_all(
    const float* __restrict__ x,
    const float* __restrict__ s0, const float* __restrict__ s1,
    const float* __restrict__ s2, const float* __restrict__ s3)
{
    int i = blockIdx.x * blockDim.x + threadIdx.x;
    if (i < XPAIRS) {
        float2 v = ((const float2*)x)[i];
        uint32_t h, l;
        split2(v.x, v.y, h, l);
        ((uint32_t*)g_xh)[i] = h;
        ((uint32_t*)g_xl)[i] = l;
    } else {
        int j = i - XPAIRS;
        int z = j / (WN_ / 2);
        int r = j - z * (WN_ / 2);
        const float* src = (z == 0) ? s0 : ((z == 1) ? s1 : ((z == 2) ? s2 : s3));
        float2 v = ((const float2*)src)[r];
        uint32_t h, l;
        split2(v.x, v.y, h, l);
        ((uint32_t*)g_Wh)[j] = h;
        ((uint32_t*)g_Wl)[j] = l;
    }
}

// ============================================================================
// pure-bf16 3-term GEMM (R9 proven, R14 fast split2)
// ============================================================================
#define AKP 40
#define BNP 136
#define OFF_AHI 0
#define OFF_ALO 5120
#define OFF_BHI 10240
#define OFF_BLO 14592
#define STG     18944
#define SMEM_G  (2 * STG * 2)

__device__ __forceinline__ void bgemm_body(
    const __nv_bfloat16* __restrict__ Ah, const __nv_bfloat16* __restrict__ Al,
    const __nv_bfloat16* __restrict__ Wh, const __nv_bfloat16* __restrict__ Wl,
    const float* __restrict__ bias,
    float* __restrict__ Cf,
    __nv_bfloat16* __restrict__ Ch, __nv_bfloat16* __restrict__ Cl,
    float scale, int bm, int bn)
{
    extern __shared__ char smg[];
    uint32_t smbase = (uint32_t)__cvta_generic_to_shared(smg);

    int tid = threadIdx.x, lane = tid & 31, wid = tid >> 5;
    int g = lane >> 2, tig = lane & 3;
    int wm = (wid & 1) * 64, wn = (wid >> 1) * 32;

    float acc[4][4][4];
#pragma unroll
    for (int mi = 0; mi < 4; mi++)
#pragma unroll
        for (int nj = 0; nj < 4; nj++)
#pragma unroll
            for (int q = 0; q < 4; q++) acc[mi][nj][q] = 0.f;

    auto issue_g = [&](int kt, int buf) {
        uint32_t sb = smbase + buf * (STG * 2);
#pragma unroll
        for (int i = 0; i < 4; i++) {
            int idx = i * 256 + tid;
            const __nv_bfloat16* base = (idx < 512) ? Ah : Al;
            uint32_t off = (idx < 512) ? OFF_AHI : OFF_ALO;
            int c = idx & 511;
            int row = c >> 2, kc = c & 3;
            cpasync16(sb + (off + row * AKP + kc * 8) * 2,
                      base + (size_t)(bm * 128 + row) * HID_ + kt * 32 + kc * 8);
        }
#pragma unroll
        for (int i = 0; i < 4; i++) {
            int idx = i * 256 + tid;
            const __nv_bfloat16* base = (idx < 512) ? Wh : Wl;
            uint32_t off = (idx < 512) ? OFF_BHI : OFF_BLO;
            int c = idx & 511;
            int row = c >> 4, nc = c & 15;
            cpasync16(sb + (off + row * BNP + nc * 8) * 2,
                      base + (size_t)(kt * 32 + row) * HID_ + bn * 128 + nc * 8);
        }
    };

    auto mma_tile = [&](int buf) {
        uint32_t abase = smbase + buf * (STG * 2);
        int arow = lane & 15;
        int asel = (lane >> 4) * 8;
#pragma unroll
        for (int ks = 0; ks < 32; ks += 16) {
            uint32_t ah[4][4], bh[4][2], bl[4][2];
            int ak = ks + asel;
            int bk = ks + (lane & 15);
#pragma unroll
            for (int mi = 0; mi < 4; mi++)
                ldsm_x4(ah[mi], abase + (uint32_t)(((wm + mi * 16 + arow) * AKP + ak) * 2));
#pragma unroll
            for (int nj = 0; nj < 4; nj++) {
                uint32_t ba = abase + (uint32_t)((bk * BNP + wn + nj * 8) * 2);
                ldsm_x2t(bh[nj], ba + OFF_BHI * 2);
                ldsm_x2t(bl[nj], ba + OFF_BLO * 2);
            }
#pragma unroll
            for (int mi = 0; mi < 4; mi++)
#pragma unroll
                for (int nj = 0; nj < 4; nj++) mma16816(acc[mi][nj], ah[mi], bh[nj][0], bh[nj][1]);
#pragma unroll
            for (int mi = 0; mi < 4; mi++)
#pragma unroll
                for (int nj = 0; nj < 4; nj++) mma16816(acc[mi][nj], ah[mi], bl[nj][0], bl[nj][1]);
#pragma unroll
            for (int mi = 0; mi < 4; mi++)
                ldsm_x4(ah[mi], abase + (uint32_t)((OFF_ALO + (wm + mi * 16 + arow) * AKP + ak) * 2));
#pragma unroll
            for (int mi = 0; mi < 4; mi++)
#pragma unroll
                for (int nj = 0; nj < 4; nj++) mma16816(acc[mi][nj], ah[mi], bh[nj][0], bh[nj][1]);
        }
    };

    issue_g(0, 0);
    asm volatile("cp.async.commit_group;");

    int buf = 0;
    for (int kt = 0; kt < HID_ / 32; kt++) {
        if (kt + 1 < HID_ / 32) {
            issue_g(kt + 1, buf ^ 1);
            asm volatile("cp.async.commit_group;");
            asm volatile("cp.async.wait_group 1;");
        } else {
            asm volatile("cp.async.wait_group 0;");
        }
        __syncthreads();
        mma_tile(buf);
        __syncthreads();
        buf ^= 1;
    }

#pragma unroll
    for (int mi = 0; mi < 4; mi++) {
#pragma unroll
        for (int nj = 0; nj < 4; nj++) {
            int m0 = bm * 128 + wm + mi * 16 + g;
            int n  = bn * 128 + wn + nj * 8 + 2 * tig;
            float bx = bias[n], by = bias[n + 1];
#pragma unroll
            for (int half = 0; half < 2; half++) {
                int m = m0 + half * 8;
                float vx = (acc[mi][nj][half * 2 + 0] + bx) * scale;
                float vy = (acc[mi][nj][half * 2 + 1] + by) * scale;
                if (Ch) {
                    int b = m >> 11, s = m & (S_ - 1);
                    int h = n >> 6, d = n & 63;
                    size_t dst = (((size_t)b * NH_ + h) * S_ + s) * HD_ + d;
                    uint32_t hi, lo;
                    split2(vx, vy, hi, lo);
                    *(uint32_t*)(Ch + dst) = hi;
                    *(uint32_t*)(Cl + dst) = lo;
                } else {
                    __stcs((float2*)(Cf + (size_t)m * HID_ + n), make_float2(vx, vy));
                }
            }
        }
    }
}

__global__ void __launch_bounds__(256, 2) bgemm_qkv(
    const float* __restrict__ b0, const float* __restrict__ b1,
    const float* __restrict__ b2)
{
    int z = blockIdx.z;
    const float* bias = (z == 0) ? b0 : ((z == 1) ? b1 : b2);
    __nv_bfloat16* Ch = (z == 0) ? g_Qh : ((z == 1) ? g_Kh : g_Vh);
    __nv_bfloat16* Cl = (z == 0) ? g_Ql : ((z == 1) ? g_Kl : g_Vl);
    float scale = (z == 0) ? 0.125f * LOG2E : 1.0f;
    bgemm_body(g_xh, g_xl, g_Wh + (size_t)z * WN_, g_Wl + (size_t)z * WN_,
               bias, nullptr, Ch, Cl, scale, blockIdx.y, blockIdx.x);
}

__global__ void __launch_bounds__(256, 2) bgemm_out(
    const float* __restrict__ bias, float* __restrict__ C)
{
    bgemm_body(g_ctxh, g_ctxl, g_Wh + (size_t)3 * WN_, g_Wl + (size_t)3 * WN_,
               bias, C, nullptr, nullptr, 1.0f, blockIdx.y, blockIdx.x);
}

// ============================================================================
// HMMA flash attention (R15 proven): 128 threads, warp m-tile 32 q rows,
// kst-major pass-2, two-pass softmax (pass1 1-term Kh-only), 2 CTAs/SM.
// ============================================================================
#define KVB   32768
#define SMEM_ATT (2 * KVB)

__device__ __forceinline__ uint32_t swz(uint32_t row, uint32_t c16)
{
    return row * 128u + (((c16) ^ (row & 7u)) << 4);
}

__global__ void __launch_bounds__(128, 2) attn_kernel(float* __restrict__ attn_out)
{
    extern __shared__ char sma[];
    uint32_t smbase = (uint32_t)__cvta_generic_to_shared(sma);
    int tid = threadIdx.x, lane = tid & 31, w = tid >> 5;
    int g = lane >> 2, tig = lane & 3;
    int qb = blockIdx.x, h = blockIdx.y, b = blockIdx.z;
    int bh = b * NH_ + h;

    {
        const __nv_bfloat16* Qhg = g_Qh + ((size_t)bh * S_ + qb * 128) * HD_;
        const __nv_bfloat16* Qlg = g_Ql + ((size_t)bh * S_ + qb * 128) * HD_;
#pragma unroll
        for (int i = 0; i < 8; i++) {
            int idx = i * 128 + tid;
            int row = idx >> 3, c16 = idx & 7;
            uint32_t off = (row >> 4) * 4096 + swz(row & 15, c16);
            *(float4*)(sma + off)        = *(const float4*)(Qhg + row * 64 + c16 * 8);
            *(float4*)(sma + off + 2048) = *(const float4*)(Qlg + row * 64 + c16 * 8);
        }
    }
    __syncthreads();

    uint32_t qh[2][4][4], ql[2][4][4];
    int li = lane >> 3;
    int rl = (lane & 7) + 8 * (li & 1);
#pragma unroll
    for (int mh = 0; mh < 2; mh++) {
        uint32_t QB = smbase + (w * 2 + mh) * 4096;
#pragma unroll
        for (int kst = 0; kst < 4; kst++) {
            int c16 = kst * 2 + (li >> 1);
            ldsm_x4(qh[mh][kst], QB + swz(rl, c16));
            ldsm_x4(ql[mh][kst], QB + 2048 + swz(rl, c16));
        }
    }
    __syncthreads();

    const size_t bhS = (size_t)bh * S_;

    auto issue_k1 = [&](int kb4, int buf) {
        const size_t tb = (bhS + kb4 * 256) * HD_;
#pragma unroll
        for (int i = 0; i < 16; i++) {
            int idx = i * 128 + tid;
            int sub = i >> 2;
            int c = idx & 511;
            int row = c >> 3, c16 = c & 7;
            uint32_t dst = smbase + buf * KVB + sub * 8192 + swz(row, c16);
            const __nv_bfloat16* src = g_Kh + tb + sub * 64 * HD_ + row * 64 + c16 * 8;
            cpasync16(dst, src);
        }
    };
    auto issue_kv = [&](int kb, int buf) {
        const size_t tb = (bhS + kb * 64) * HD_;
#pragma unroll
        for (int i = 0; i < 16; i++) {
            int idx = i * 128 + tid;
            int arr = i >> 2;
            int c = idx & 511;
            int row = c >> 3, c16 = c & 7;
            uint32_t dst = smbase + buf * KVB + arr * 8192 + swz(row, c16);
            const __nv_bfloat16* src;
            if      (arr == 0) src = g_Kh + tb;
            else if (arr == 1) src = g_Kl + tb;
            else if (arr == 2) src = g_Vh + tb;
            else               src = g_Vl + tb;
            src += row * 64 + c16 * 8;
            cpasync16(dst, src);
        }
    };

    // ====== PASS 1: rowsums (1-term, Kh only), 8 its x 256 K rows ======
    float rs[2][2] = {{0.f, 0.f}, {0.f, 0.f}};
    {
        issue_k1(0, 0);
        asm volatile("cp.async.commit_group;");
        int buf = 0;
        for (int kb = 0; kb < 8; kb++) {
            if (kb) __syncthreads();
            if (kb + 1 < 8) {
                issue_k1(kb + 1, buf ^ 1);
                asm volatile("cp.async.commit_group;");
                asm volatile("cp.async.wait_group 1;");
            } else {
                asm volatile("cp.async.wait_group 0;");
            }
            __syncthreads();
            uint32_t kvb = smbase + buf * KVB;
#pragma unroll
            for (int sub = 0; sub < 4; sub++) {
                float sacc[2][8][4];
#pragma unroll
                for (int mh = 0; mh < 2; mh++)
#pragma unroll
                    for (int nt = 0; nt < 8; nt++)
#pragma unroll
                        for (int q = 0; q < 4; q++) sacc[mh][nt][q] = 0.f;
#pragma unroll
                for (int kst = 0; kst < 4; kst++) {
                    int kc = kst * 2 + (li >> 1);
#pragma unroll
                    for (int np = 0; np < 4; np++) {
                        uint32_t kh4[4];
                        ldsm_x4(kh4, kvb + sub * 8192 + swz(np * 16 + rl, kc));
#pragma unroll
                        for (int mh = 0; mh < 2; mh++) {
                            mma16816(sacc[mh][2 * np],     qh[mh][kst], kh4[0], kh4[2]);
                            mma16816(sacc[mh][2 * np + 1], qh[mh][kst], kh4[1], kh4[3]);
                        }
                    }
                }
#pragma unroll
                for (int mh = 0; mh < 2; mh++)
#pragma unroll
                    for (int nt = 0; nt < 8; nt++) {
                        rs[mh][0] += ex2f(sacc[mh][nt][0]) + ex2f(sacc[mh][nt][1]);
                        rs[mh][1] += ex2f(sacc[mh][nt][2]) + ex2f(sacc[mh][nt][3]);
                    }
            }
            buf ^= 1;
        }
    }
    float inv[2][2];
#pragma unroll
    for (int mh = 0; mh < 2; mh++)
#pragma unroll
        for (int j = 0; j < 2; j++) {
            float v = rs[mh][j];
            v += __shfl_xor_sync(0xffffffffu, v, 1);
            v += __shfl_xor_sync(0xffffffffu, v, 2);
            inv[mh][j] = 1.0f / v;
        }
    __syncthreads();

    // ====== PASS 2: normalized attn + ctx, per-kst exp/PV pipeline ======
    float ctx[2][8][4];
#pragma unroll
    for (int mh = 0; mh < 2; mh++)
#pragma unroll
        for (int nt = 0; nt < 8; nt++)
#pragma unroll
            for (int q = 0; q < 4; q++) ctx[mh][nt][q] = 0.f;

    issue_kv(0, 0);
    asm volatile("cp.async.commit_group;");
    int buf = 0;
    for (int kb = 0; kb < S_ / 64; kb++) {
        if (kb) __syncthreads();
        if (kb + 1 < S_ / 64) {
            issue_kv(kb + 1, buf ^ 1);
            asm volatile("cp.async.commit_group;");
            asm volatile("cp.async.wait_group 1;");
        } else {
            asm volatile("cp.async.wait_group 0;");
        }
        __syncthreads();

        uint32_t kvb = smbase + buf * KVB;

        float sacc[2][8][4];
#pragma unroll
        for (int mh = 0; mh < 2; mh++)
#pragma unroll
            for (int nt = 0; nt < 8; nt++)
#pragma unroll
                for (int q = 0; q < 4; q++) sacc[mh][nt][q] = 0.f;
#pragma unroll
        for (int kst = 0; kst < 4; kst++) {
            int kc = kst * 2 + (li >> 1);
#pragma unroll
            for (int np = 0; np < 4; np++) {
                uint32_t kh4[4], kl4[4];
                ldsm_x4(kh4, kvb +        swz(np * 16 + rl, kc));
                ldsm_x4(kl4, kvb + 8192 + swz(np * 16 + rl, kc));
#pragma unroll
                for (int mh = 0; mh < 2; mh++) {
                    mma16816(sacc[mh][2 * np],     qh[mh][kst], kh4[0], kh4[2]);
                    mma16816(sacc[mh][2 * np + 1], qh[mh][kst], kh4[1], kh4[3]);
                    mma16816(sacc[mh][2 * np],     qh[mh][kst], kl4[0], kl4[2]);
                    mma16816(sacc[mh][2 * np + 1], qh[mh][kst], kl4[1], kl4[3]);
                    mma16816(sacc[mh][2 * np],     ql[mh][kst], kh4[0], kh4[2]);
                    mma16816(sacc[mh][2 * np + 1], ql[mh][kst], kh4[1], kh4[3]);
                }
            }
        }

        float* attp0 = nullptr;
        if (attn_out)
            attp0 = attn_out + (bhS + qb * 128 + w * 32 + g) * S_ + kb * 64 + 2 * tig;

#pragma unroll
        for (int kst = 0; kst < 4; kst++) {
            uint32_t pah[2][4], pal[2][4];
#pragma unroll
            for (int mh = 0; mh < 2; mh++) {
                float* attp = attp0 ? attp0 + mh * 16 * S_ : nullptr;
#pragma unroll
                for (int half = 0; half < 2; half++) {
                    int nt = 2 * kst + half;
                    float p0 = ex2f(sacc[mh][nt][0]) * inv[mh][0];
                    float p1 = ex2f(sacc[mh][nt][1]) * inv[mh][0];
                    float p2 = ex2f(sacc[mh][nt][2]) * inv[mh][1];
                    float p3 = ex2f(sacc[mh][nt][3]) * inv[mh][1];
                    if (attp) {
                        __stcs((float2*)(attp + nt * 8),          make_float2(p0, p1));
                        __stcs((float2*)(attp + 8 * S_ + nt * 8), make_float2(p2, p3));
                    }
                    uint32_t h01, l01, h23, l23;
                    split2(p0, p1, h01, l01);
                    split2(p2, p3, h23, l23);
                    pah[mh][half * 2 + 0] = h01;
                    pah[mh][half * 2 + 1] = h23;
                    pal[mh][half * 2 + 0] = l01;
                    pal[mh][half * 2 + 1] = l23;
                }
            }

            int vr = kst * 16 + (lane & 7) + 8 * (li & 1);
#pragma unroll
            for (int np = 0; np < 4; np++) {
                uint32_t vh4[4], vl4[4];
                int vc = np * 2 + (li >> 1);
                ldsm_x4t(vh4, kvb + 16384 + swz(vr, vc));
                ldsm_x4t(vl4, kvb + 24576 + swz(vr, vc));
#pragma unroll
                for (int mh = 0; mh < 2; mh++) {
                    mma16816(ctx[mh][2 * np],     pah[mh], vh4[0], vh4[1]);
                    mma16816(ctx[mh][2 * np + 1], pah[mh], vh4[2], vh4[3]);
                    mma16816(ctx[mh][2 * np],     pah[mh], vl4[0], vl4[1]);
                    mma16816(ctx[mh][2 * np + 1], pah[mh], vl4[2], vl4[3]);
                    mma16816(ctx[mh][2 * np],     pal[mh], vh4[0], vh4[1]);
                    mma16816(ctx[mh][2 * np + 1], pal[mh], vh4[2], vh4[3]);
                }
            }
        }
        buf ^= 1;
    }

    // ---- store ctx (already normalized) as split bf16 ----
#pragma unroll
    for (int mh = 0; mh < 2; mh++) {
        int qrow0 = qb * 128 + w * 32 + mh * 16 + g;
        size_t base0 = ((size_t)b * S_ + qrow0) * HID_ + h * HD_ + 2 * tig;
#pragma unroll
        for (int nt = 0; nt < 8; nt++) {
            uint32_t hi, lo;
            split2(ctx[mh][nt][0], ctx[mh][nt][1], hi, lo);
            *(uint32_t*)(g_ctxh + base0 + nt * 8) = hi;
            *(uint32_t*)(g_ctxl + base0 + nt * 8) = lo;
            split2(ctx[mh][nt][2], ctx[mh][nt][3], hi, lo);
            *(uint32_t*)(g_ctxh + base0 + 8 * HID_ + nt * 8) = hi;
            *(uint32_t*)(g_ctxl + base0 + 8 * HID_ + nt * 8) = lo;
        }
    }
}

// ---------------- launch ---------------------------------------------------
extern "C" void kernel_launch(void* const* d_in, const int* in_sizes, int n_in,
                              void* d_out, int out_size)
{
    const float* x  = (const float*)d_in[0];
    const float* Wq = (const float*)d_in[1];
    const float* bq = (const float*)d_in[2];
    const float* Wk = (const float*)d_in[3];
    const float* bk = (const float*)d_in[4];
    const float* Wv = (const float*)d_in[5];
    const float* bv = (const float*)d_in[6];
    const float* Wo = (const float*)d_in[7];
    const float* bo = (const float*)d_in[8];

    float* out = (float*)d_out;
    const size_t OUT_E = (size_t)B_ * S_ * HID_;
    const size_t ATT_E = (size_t)B_ * NH_ * S_ * S_;
    float* attn = ((size_t)out_size >= OUT_E + ATT_E) ? (out + OUT_E) : nullptr;

    cudaFuncSetAttribute(attn_kernel,
                         cudaFuncAttributeMaxDynamicSharedMemorySize, SMEM_ATT);
    cudaFuncSetAttribute(bgemm_qkv,
                         cudaFuncAttributeMaxDynamicSharedMemorySize, SMEM_G);
    cudaFuncSetAttribute(bgemm_out,
                         cudaFuncAttributeMaxDynamicSharedMemorySize, SMEM_G);

    split_all<<<(XPAIRS + WPAIRS) / 256, 256>>>(x, Wq, Wk, Wv, Wo);

    dim3 g1(HID_ / 128, M_ / 128, 3);
    bgemm_qkv<<<g1, 256, SMEM_G>>>(bq, bk, bv);

    dim3 g2(S_ / 128, NH_, B_);
    attn_kernel<<<g2, 128, SMEM_ATT>>>(attn);

    dim3 g3(HID_ / 128, M_ / 128);
    bgemm_out<<<g3, 256, SMEM_G>>>(bo, out);
}